// round 8
// baseline (speedup 1.0000x reference)
#include <cuda_runtime.h>
#include <stdint.h>

// Shapes (fixed):
//   lstm : [4, 256, 128] f32   (512 KiB -> L1/L2 resident)
//   slic : [4, 512, 512] i32   (4 MiB)
//   out  : [4, 512, 512, 128] f32 (512 MiB written -> the bound)
//
// R7: 8 pixels per warp (was 4). All 8 slic ids come from two warp-uniform
// int4 loads; 8 independent gathers; 8 independent streaming stores (4 KB
// contiguous per warp). Goal: more in-flight bytes per warp to close the
// 6.08 -> ~6.8 TB/s gap (kernel is still latency-exposed: issue=13%,
// no pipe saturated).

namespace {
constexpr int S = 256;
constexpr int C = 128;                 // floats per pixel row
constexpr int HW_SHIFT = 18;           // 512*512 = 1<<18
constexpr long long NPIX = 4LL << HW_SHIFT;   // 1,048,576
constexpr int PIX_PER_WARP = 8;
constexpr int WARPS_PER_BLOCK = 8;     // 256 threads
constexpr int THREADS = WARPS_PER_BLOCK * 32;
constexpr int PIX_PER_BLOCK = WARPS_PER_BLOCK * PIX_PER_WARP;   // 64
}

__global__ __launch_bounds__(THREADS)
void convert2image_gather8(const float* __restrict__ lstm,
                           const int*   __restrict__ slic,
                           float*       __restrict__ out)
{
    const int lane = threadIdx.x & 31;
    const int warp = threadIdx.x >> 5;

    // First pixel of this warp's group of 8 (consecutive, 16B-aligned ids).
    const long long p0 = ((long long)blockIdx.x * WARPS_PER_BLOCK + warp)
                         * PIX_PER_WARP;

    // Whole group shares one batch (p0 % 8 == 0, HW % 8 == 0).
    const int b = (int)(p0 >> HW_SHIFT);
    const float* __restrict__ lstm_b = lstm + (long long)b * S * C;

    // 1) Two warp-uniform int4 loads cover all 8 segment ids.
    const int4* sp = reinterpret_cast<const int4*>(slic + p0);
    const int4 s0 = __ldg(&sp[0]);
    const int4 s1 = __ldg(&sp[1]);
    int seg[PIX_PER_WARP] = { s0.x - 1, s0.y - 1, s0.z - 1, s0.w - 1,
                              s1.x - 1, s1.y - 1, s1.z - 1, s1.w - 1 };

    // 2) Eight independent gather loads (lstm rows are L1 hits when warm).
    float4 v[PIX_PER_WARP];
#pragma unroll
    for (int i = 0; i < PIX_PER_WARP; ++i) {
        const float4* src =
            reinterpret_cast<const float4*>(lstm_b + (long long)seg[i] * C);
        v[i] = __ldg(&src[lane]);
    }

    // 3) Eight independent streaming stores: warp writes 4 KB contiguous.
    float4* __restrict__ dst =
        reinterpret_cast<float4*>(out + p0 * (long long)C);
#pragma unroll
    for (int i = 0; i < PIX_PER_WARP; ++i)
        __stcs(&dst[i * 32 + lane], v[i]);
}

extern "C" void kernel_launch(void* const* d_in, const int* in_sizes, int n_in,
                              void* d_out, int out_size)
{
    const float* lstm = (const float*)d_in[0];
    const int*   slic = (const int*)d_in[1];
    float*       out  = (float*)d_out;

    (void)in_sizes; (void)n_in; (void)out_size;

    const int grid = (int)(NPIX / PIX_PER_BLOCK);   // 16384, exact
    convert2image_gather8<<<grid, THREADS>>>(lstm, slic, out);
}

// round 9
// speedup vs baseline: 1.0167x; 1.0167x over previous
#include <cuda_runtime.h>
#include <stdint.h>

// Shapes (fixed):
//   lstm : [4, 256, 128] f32   (512 KiB -> L1/L2 resident)
//   slic : [4, 512, 512] i32   (4 MiB, read once)
//   out  : [4, 512, 512, 128] f32 (512 MiB written -> the binding stream)
//
// R8: best-known config (P=4 pixels/warp) + cleanups:
//   - one warp-uniform int4 load fetches all 4 segment ids (was 4 scalar LDGs)
//   - 512-thread blocks (16 warps) for coarser scheduling granularity
//   - __stcs streaming stores (write-once stream, protect lstm in L2)
// We are ~90% of effective HBM write roofline; this round shaves issue/load
// overhead rather than adding MLP (R7 showed MLP is saturated).

namespace {
constexpr int S = 256;
constexpr int C = 128;                 // floats per pixel row
constexpr int HW_SHIFT = 18;           // 512*512 = 1<<18
constexpr long long NPIX = 4LL << HW_SHIFT;   // 1,048,576
constexpr int PIX_PER_WARP = 4;
constexpr int WARPS_PER_BLOCK = 16;    // 512 threads
constexpr int THREADS = WARPS_PER_BLOCK * 32;
constexpr int PIX_PER_BLOCK = WARPS_PER_BLOCK * PIX_PER_WARP;   // 64
}

__global__ __launch_bounds__(THREADS)
void convert2image_gather4b(const float* __restrict__ lstm,
                            const int*   __restrict__ slic,
                            float*       __restrict__ out)
{
    const int lane = threadIdx.x & 31;
    const int warp = threadIdx.x >> 5;

    // First pixel of this warp's group of 4 (consecutive, 16B-aligned ids).
    const long long p0 = ((long long)blockIdx.x * WARPS_PER_BLOCK + warp)
                         * PIX_PER_WARP;

    // Group shares one batch (p0 % 4 == 0, HW % 4 == 0).
    const int b = (int)(p0 >> HW_SHIFT);
    const float* __restrict__ lstm_b = lstm + (long long)b * S * C;

    // 1) One warp-uniform int4 load covers all 4 segment ids.
    const int4 s = __ldg(reinterpret_cast<const int4*>(slic + p0));
    const int seg[PIX_PER_WARP] = { s.x - 1, s.y - 1, s.z - 1, s.w - 1 };

    // 2) Four independent gather loads (lstm rows are L1/L2 hits when warm).
    float4 v[PIX_PER_WARP];
#pragma unroll
    for (int i = 0; i < PIX_PER_WARP; ++i) {
        const float4* src =
            reinterpret_cast<const float4*>(lstm_b + (long long)seg[i] * C);
        v[i] = __ldg(&src[lane]);
    }

    // 3) Four independent streaming stores: warp writes 2 KB contiguous.
    float4* __restrict__ dst =
        reinterpret_cast<float4*>(out + p0 * (long long)C);
#pragma unroll
    for (int i = 0; i < PIX_PER_WARP; ++i)
        __stcs(&dst[i * 32 + lane], v[i]);
}

extern "C" void kernel_launch(void* const* d_in, const int* in_sizes, int n_in,
                              void* d_out, int out_size)
{
    const float* lstm = (const float*)d_in[0];
    const int*   slic = (const int*)d_in[1];
    float*       out  = (float*)d_out;

    (void)in_sizes; (void)n_in; (void)out_size;

    const int grid = (int)(NPIX / PIX_PER_BLOCK);   // 16384, exact
    convert2image_gather4b<<<grid, THREADS>>>(lstm, slic, out);
}